// round 2
// baseline (speedup 1.0000x reference)
#include <cuda_runtime.h>
#include <cstdint>

#define BATCH 4
#define CDIM 256
#define HH 128
#define WW 128
#define NPIX (HH*WW)
#define HEADS 8
#define DHEAD 32
#define BLK 8
#define HALO 3
#define WINS 14
#define NBH 16
#define NBW 16
#define NBLK 256
#define NQ 64
#define NKEY 196

// -------- scratch (static device allocations; no cudaMalloc anywhere) --------
__device__ float g_q  [(size_t)BATCH * CDIM     * NPIX];     // [b][c][h][w]
__device__ float g_kv [(size_t)BATCH * 2 * CDIM * NPIX];     // [b][c][h][w]
__device__ float g_ctx[(size_t)BATCH * NBLK * NQ * CDIM];    // [b][n][q][c]

// ============================================================================
// Generic NN GEMM: C[b][m][n] = sum_k A[m][k] * B[b][k][n]
// A row-major [M,K]; B row-major [K,N] per batch; tile 64x64x16, 256 threads.
// ============================================================================
__global__ __launch_bounds__(256) void gemm_nn(const float* __restrict__ A,
                                               const float* __restrict__ Bmat,
                                               float* __restrict__ Cmat,
                                               int M, int N, int K) {
    __shared__ __align__(16) float As[16][68];
    __shared__ __align__(16) float Bs[16][68];

    const int bz = blockIdx.z;
    const float* Bp = Bmat + (size_t)bz * K * N;
    float* Cp = Cmat + (size_t)bz * M * N;

    const int m0 = blockIdx.y * 64;
    const int n0 = blockIdx.x * 64;
    const int tid = threadIdx.x;
    const int tx = tid & 15, ty = tid >> 4;

    const int arow = tid >> 2;          // 0..63
    const int acol = (tid & 3) * 4;     // 0..12
    const int brow = tid >> 4;          // 0..15
    const int bcol = (tid & 15) * 4;    // 0..60

    float acc[4][4];
    #pragma unroll
    for (int i = 0; i < 4; i++)
        #pragma unroll
        for (int j = 0; j < 4; j++) acc[i][j] = 0.f;

    for (int k0 = 0; k0 < K; k0 += 16) {
        float4 av = *(const float4*)&A[(size_t)(m0 + arow) * K + k0 + acol];
        As[acol + 0][arow] = av.x;
        As[acol + 1][arow] = av.y;
        As[acol + 2][arow] = av.z;
        As[acol + 3][arow] = av.w;
        float4 bv = *(const float4*)&Bp[(size_t)(k0 + brow) * N + n0 + bcol];
        *(float4*)&Bs[brow][bcol] = bv;
        __syncthreads();
        #pragma unroll
        for (int kk = 0; kk < 16; kk++) {
            float4 a4 = *(const float4*)&As[kk][ty * 4];
            float4 b4 = *(const float4*)&Bs[kk][tx * 4];
            float av_[4] = {a4.x, a4.y, a4.z, a4.w};
            float bv_[4] = {b4.x, b4.y, b4.z, b4.w};
            #pragma unroll
            for (int i = 0; i < 4; i++)
                #pragma unroll
                for (int j = 0; j < 4; j++) acc[i][j] += av_[i] * bv_[j];
        }
        __syncthreads();
    }

    #pragma unroll
    for (int i = 0; i < 4; i++) {
        float4 v = make_float4(acc[i][0], acc[i][1], acc[i][2], acc[i][3]);
        *(float4*)&Cp[(size_t)(m0 + ty * 4 + i) * N + n0 + tx * 4] = v;
    }
}

// ============================================================================
// FC GEMM (NT) + bias + scatter:
//   out[p][o] = sum_c ctx[p][c] * fc_w[o][c] + fc_b[o], scattered to BCHW.
// M-dim = o (grid.y), N-dim = p (grid.x). Both operands K-contiguous.
// ============================================================================
__global__ __launch_bounds__(256) void gemm_fc(const float* __restrict__ Wf,
                                               const float* __restrict__ fcb,
                                               float* __restrict__ out) {
    __shared__ __align__(16) float As[16][68];
    __shared__ __align__(16) float Bs[16][68];

    const int m0 = blockIdx.y * 64;     // output channel tile
    const int n0 = blockIdx.x * 64;     // pixel tile
    const int tid = threadIdx.x;
    const int tx = tid & 15, ty = tid >> 4;

    const int lrow = tid >> 2;          // 0..63
    const int lcol = (tid & 3) * 4;

    float acc[4][4];
    #pragma unroll
    for (int i = 0; i < 4; i++)
        #pragma unroll
        for (int j = 0; j < 4; j++) acc[i][j] = 0.f;

    for (int k0 = 0; k0 < CDIM; k0 += 16) {
        float4 av = *(const float4*)&Wf[(size_t)(m0 + lrow) * CDIM + k0 + lcol];
        As[lcol + 0][lrow] = av.x;
        As[lcol + 1][lrow] = av.y;
        As[lcol + 2][lrow] = av.z;
        As[lcol + 3][lrow] = av.w;
        float4 bv = *(const float4*)&g_ctx[(size_t)(n0 + lrow) * CDIM + k0 + lcol];
        Bs[lcol + 0][lrow] = bv.x;
        Bs[lcol + 1][lrow] = bv.y;
        Bs[lcol + 2][lrow] = bv.z;
        Bs[lcol + 3][lrow] = bv.w;
        __syncthreads();
        #pragma unroll
        for (int kk = 0; kk < 16; kk++) {
            float4 a4 = *(const float4*)&As[kk][ty * 4];
            float4 b4 = *(const float4*)&Bs[kk][tx * 4];
            float av_[4] = {a4.x, a4.y, a4.z, a4.w};
            float bv_[4] = {b4.x, b4.y, b4.z, b4.w};
            #pragma unroll
            for (int i = 0; i < 4; i++)
                #pragma unroll
                for (int j = 0; j < 4; j++) acc[i][j] += av_[i] * bv_[j];
        }
        __syncthreads();
    }

    #pragma unroll
    for (int i = 0; i < 4; i++) {
        const int o = m0 + ty * 4 + i;
        const float bias = fcb[o];
        #pragma unroll
        for (int j = 0; j < 4; j++) {
            const int p = n0 + tx * 4 + j;
            const int b = p >> 14;                // / (256*64)
            const int n = (p >> 6) & 255;
            const int q = p & 63;
            const int row = ((n >> 4) << 3) + (q >> 3);
            const int col = ((n & 15) << 3) + (q & 7);
            out[(((size_t)b * CDIM + o) << 14) + (row << 7) + col] = acc[i][j] + bias;
        }
    }
}

// ============================================================================
// Fused halo attention: one CTA per (b, block, head). 256 threads.
// thread = q*4 + g;  each thread handles query q and key group g (49 keys).
// ============================================================================
#define ATT_SMEM_FLOATS (64*36 + 2*196*36 + 2*64*14 + 2*27*32)

__global__ __launch_bounds__(256) void halo_attn(const float* __restrict__ rel_h,
                                                 const float* __restrict__ rel_w) {
    extern __shared__ __align__(16) float sm[];
    float* qs  = sm;                 // [64][36]
    float* ks  = qs + 64 * 36;       // [196][36]
    float* vs  = ks + 196 * 36;      // [196][36]
    float* bwv = vs + 196 * 36;      // [64][14]
    float* bhv = bwv + 64 * 14;      // [64][14]
    float* rhs = bhv + 64 * 14;      // [27][32]
    float* rws = rhs + 27 * 32;      // [27][32]

    const int bid = blockIdx.x;
    const int h = bid & 7;
    const int n = (bid >> 3) & 255;
    const int b = bid >> 11;
    const int r0 = (n >> 4) << 3;    // block row origin
    const int c0 = (n & 15) << 3;    // block col origin
    const int tid = threadIdx.x;

    // ---- load q tile ----
    const float* qbase = g_q + ((size_t)b * CDIM + h * DHEAD) * NPIX;
    for (int idx = tid; idx < 64 * 32; idx += 256) {
        const int d = idx >> 6, q = idx & 63;
        const int row = r0 + (q >> 3), col = c0 + (q & 7);
        qs[q * 36 + d] = qbase[d * NPIX + row * WW + col];
    }
    // ---- load k/v window with zero halo padding ----
    const float* kbase = g_kv + ((size_t)b * 2 * CDIM + h * DHEAD) * NPIX;
    const float* vbase = kbase + (size_t)CDIM * NPIX;
    for (int idx = tid; idx < NKEY * 32; idx += 256) {
        const int d = idx / NKEY, kj = idx % NKEY;
        const int rr = r0 - HALO + kj / WINS;
        const int cc = c0 - HALO + kj % WINS;
        float kval = 0.f, vval = 0.f;
        if (rr >= 0 && rr < HH && cc >= 0 && cc < WW) {
            const int off = d * NPIX + rr * WW + cc;
            kval = kbase[off];
            vval = vbase[off];
        }
        ks[kj * 36 + d] = kval;
        vs[kj * 36 + d] = vval;
    }
    // ---- rel tables ----
    for (int idx = tid; idx < 27 * 32; idx += 256) {
        rhs[idx] = rel_h[idx];
        rws[idx] = rel_w[idx];
    }
    __syncthreads();

    // ---- per-query relative bias vectors ----
    for (int idx = tid; idx < 64 * WINS; idx += 256) {
        const int q = idx / WINS, j = idx % WINS;
        const int y = q & 7, x = q >> 3;
        const float* qrow = &qs[q * 36];
        const float* rw = &rws[(j - y + WINS - 1) * 32];
        const float* rh = &rhs[(j - x + WINS - 1) * 32];
        float sw = 0.f, sh = 0.f;
        #pragma unroll
        for (int d = 0; d < 32; d++) {
            sw += qrow[d] * rw[d];
            sh += qrow[d] * rh[d];
        }
        bwv[idx] = sw;   // bwv[q][j]
        bhv[idx] = sh;   // bhv[q][i]
    }
    __syncthreads();

    const int q = tid >> 2;
    const int g = tid & 3;

    float qreg[32];
    {
        const float4* q4 = (const float4*)(qs + q * 36);
        #pragma unroll
        for (int d4 = 0; d4 < 8; d4++) {
            float4 v = q4[d4];
            qreg[d4 * 4 + 0] = v.x; qreg[d4 * 4 + 1] = v.y;
            qreg[d4 * 4 + 2] = v.z; qreg[d4 * 4 + 3] = v.w;
        }
    }

    const float scale = 0.17677669529663687f;  // 1/sqrt(32)
    float sarr[49];
    #pragma unroll
    for (int t = 0; t < 49; t++) {
        const int k = g * 49 + t;
        const float4* k4 = (const float4*)(ks + k * 36);
        float a = 0.f;
        #pragma unroll
        for (int d4 = 0; d4 < 8; d4++) {
            float4 kv4 = k4[d4];
            a += qreg[d4 * 4 + 0] * kv4.x + qreg[d4 * 4 + 1] * kv4.y
               + qreg[d4 * 4 + 2] * kv4.z + qreg[d4 * 4 + 3] * kv4.w;
        }
        sarr[t] = a * scale + bwv[q * WINS + (k % WINS)] + bhv[q * WINS + (k / WINS)];
    }

    // ---- softmax across the 4 threads sharing this query ----
    float m = -1e30f;
    #pragma unroll
    for (int t = 0; t < 49; t++) m = fmaxf(m, sarr[t]);
    m = fmaxf(m, __shfl_xor_sync(0xffffffffu, m, 1));
    m = fmaxf(m, __shfl_xor_sync(0xffffffffu, m, 2));
    float sum = 0.f;
    #pragma unroll
    for (int t = 0; t < 49; t++) {
        sarr[t] = __expf(sarr[t] - m);
        sum += sarr[t];
    }
    sum += __shfl_xor_sync(0xffffffffu, sum, 1);
    sum += __shfl_xor_sync(0xffffffffu, sum, 2);
    const float inv = 1.f / sum;

    // ---- ctx = att @ v (partial over this thread's 49 keys) ----
    float acc[32];
    #pragma unroll
    for (int d = 0; d < 32; d++) acc[d] = 0.f;
    #pragma unroll
    for (int t = 0; t < 49; t++) {
        const float p = sarr[t];
        const float4* v4 = (const float4*)(vs + (g * 49 + t) * 36);
        #pragma unroll
        for (int d4 = 0; d4 < 8; d4++) {
            float4 vv = v4[d4];
            acc[d4 * 4 + 0] += p * vv.x;
            acc[d4 * 4 + 1] += p * vv.y;
            acc[d4 * 4 + 2] += p * vv.z;
            acc[d4 * 4 + 3] += p * vv.w;
        }
    }
    #pragma unroll
    for (int d = 0; d < 32; d++) {
        acc[d] += __shfl_xor_sync(0xffffffffu, acc[d], 1);
        acc[d] += __shfl_xor_sync(0xffffffffu, acc[d], 2);
    }

    if (g == 0) {
        float* cdst = g_ctx + (((size_t)(b * NBLK + n) * NQ + q) * CDIM + h * DHEAD);
        #pragma unroll
        for (int d4 = 0; d4 < 8; d4++) {
            ((float4*)cdst)[d4] = make_float4(acc[d4 * 4 + 0] * inv, acc[d4 * 4 + 1] * inv,
                                              acc[d4 * 4 + 2] * inv, acc[d4 * 4 + 3] * inv);
        }
    }
}

// ============================================================================
extern "C" void kernel_launch(void* const* d_in, const int* in_sizes, int n_in,
                              void* d_out, int out_size) {
    const float* x     = (const float*)d_in[0];
    const float* w_q   = (const float*)d_in[1];
    const float* w_kv  = (const float*)d_in[2];
    const float* fc_w  = (const float*)d_in[3];
    const float* fc_b  = (const float*)d_in[4];
    const float* rel_h = (const float*)d_in[5];
    const float* rel_w = (const float*)d_in[6];
    float* out = (float*)d_out;

    float *gq, *gkv;
    cudaGetSymbolAddress((void**)&gq, g_q);
    cudaGetSymbolAddress((void**)&gkv, g_kv);

    const int att_smem = ATT_SMEM_FLOATS * (int)sizeof(float);
    cudaFuncSetAttribute(halo_attn, cudaFuncAttributeMaxDynamicSharedMemorySize, att_smem);

    // q projection: M=256, N=16384, K=256
    gemm_nn<<<dim3(NPIX / 64, CDIM / 64, BATCH), 256>>>(w_q, x, gq, CDIM, NPIX, CDIM);
    // kv projection: M=512
    gemm_nn<<<dim3(NPIX / 64, (2 * CDIM) / 64, BATCH), 256>>>(w_kv, x, gkv, 2 * CDIM, NPIX, CDIM);
    // fused attention: one CTA per (b, block, head)
    halo_attn<<<BATCH * NBLK * HEADS, 256, att_smem>>>(rel_h, rel_w);
    // FC + bias + scatter to BCHW
    gemm_fc<<<dim3((BATCH * NBLK * NQ) / 64, CDIM / 64), 256>>>(fc_w, fc_b, out);
}

// round 3
// speedup vs baseline: 1.0005x; 1.0005x over previous
#include <cuda_runtime.h>
#include <cstdint>

#define BATCH 4
#define CDIM 256
#define HH 128
#define WW 128
#define NPIX (HH*WW)
#define HEADS 8
#define DHEAD 32
#define BLK 8
#define HALO 3
#define WINS 14
#define NBH 16
#define NBW 16
#define NBLK 256
#define NQ 64
#define NKEY 196

// -------- scratch (static device allocations; no cudaMalloc anywhere) --------
__device__ float g_q  [(size_t)BATCH * CDIM     * NPIX];     // [b][c][h][w]
__device__ float g_kv [(size_t)BATCH * 2 * CDIM * NPIX];     // [b][c][h][w]
__device__ float g_ctx[(size_t)BATCH * NBLK * NQ * CDIM];    // [b][n][q][c]

// ============================================================================
// Generic NN GEMM: C[b][m][n] = sum_k A[m][k] * B[b][k][n]
// A row-major [M,K]; B row-major [K,N] per batch; tile 64x64x16, 256 threads.
// ============================================================================
__global__ __launch_bounds__(256) void gemm_nn(const float* __restrict__ A,
                                               const float* __restrict__ Bmat,
                                               float* __restrict__ Cmat,
                                               int M, int N, int K) {
    __shared__ __align__(16) float As[16][68];
    __shared__ __align__(16) float Bs[16][68];

    const int bz = blockIdx.z;
    const float* Bp = Bmat + (size_t)bz * K * N;
    float* Cp = Cmat + (size_t)bz * M * N;

    const int m0 = blockIdx.y * 64;
    const int n0 = blockIdx.x * 64;
    const int tid = threadIdx.x;
    const int tx = tid & 15, ty = tid >> 4;

    const int arow = tid >> 2;          // 0..63
    const int acol = (tid & 3) * 4;     // 0..12
    const int brow = tid >> 4;          // 0..15
    const int bcol = (tid & 15) * 4;    // 0..60

    float acc[4][4];
    #pragma unroll
    for (int i = 0; i < 4; i++)
        #pragma unroll
        for (int j = 0; j < 4; j++) acc[i][j] = 0.f;

    for (int k0 = 0; k0 < K; k0 += 16) {
        float4 av = *(const float4*)&A[(size_t)(m0 + arow) * K + k0 + acol];
        As[acol + 0][arow] = av.x;
        As[acol + 1][arow] = av.y;
        As[acol + 2][arow] = av.z;
        As[acol + 3][arow] = av.w;
        float4 bv = *(const float4*)&Bp[(size_t)(k0 + brow) * N + n0 + bcol];
        *(float4*)&Bs[brow][bcol] = bv;
        __syncthreads();
        #pragma unroll
        for (int kk = 0; kk < 16; kk++) {
            float4 a4 = *(const float4*)&As[kk][ty * 4];
            float4 b4 = *(const float4*)&Bs[kk][tx * 4];
            float av_[4] = {a4.x, a4.y, a4.z, a4.w};
            float bv_[4] = {b4.x, b4.y, b4.z, b4.w};
            #pragma unroll
            for (int i = 0; i < 4; i++)
                #pragma unroll
                for (int j = 0; j < 4; j++) acc[i][j] += av_[i] * bv_[j];
        }
        __syncthreads();
    }

    #pragma unroll
    for (int i = 0; i < 4; i++) {
        float4 v = make_float4(acc[i][0], acc[i][1], acc[i][2], acc[i][3]);
        *(float4*)&Cp[(size_t)(m0 + ty * 4 + i) * N + n0 + tx * 4] = v;
    }
}

// ============================================================================
// FC GEMM (NT) + bias + scatter:
//   out[p][o] = sum_c ctx[p][c] * fc_w[o][c] + fc_b[o], scattered to BCHW.
// M-dim = o (grid.y), N-dim = p (grid.x). Both operands K-contiguous.
// ============================================================================
__global__ __launch_bounds__(256) void gemm_fc(const float* __restrict__ Wf,
                                               const float* __restrict__ fcb,
                                               float* __restrict__ out) {
    __shared__ __align__(16) float As[16][68];
    __shared__ __align__(16) float Bs[16][68];

    const int m0 = blockIdx.y * 64;     // output channel tile
    const int n0 = blockIdx.x * 64;     // pixel tile
    const int tid = threadIdx.x;
    const int tx = tid & 15, ty = tid >> 4;

    const int lrow = tid >> 2;          // 0..63
    const int lcol = (tid & 3) * 4;

    float acc[4][4];
    #pragma unroll
    for (int i = 0; i < 4; i++)
        #pragma unroll
        for (int j = 0; j < 4; j++) acc[i][j] = 0.f;

    for (int k0 = 0; k0 < CDIM; k0 += 16) {
        float4 av = *(const float4*)&Wf[(size_t)(m0 + lrow) * CDIM + k0 + lcol];
        As[lcol + 0][lrow] = av.x;
        As[lcol + 1][lrow] = av.y;
        As[lcol + 2][lrow] = av.z;
        As[lcol + 3][lrow] = av.w;
        float4 bv = *(const float4*)&g_ctx[(size_t)(n0 + lrow) * CDIM + k0 + lcol];
        Bs[lcol + 0][lrow] = bv.x;
        Bs[lcol + 1][lrow] = bv.y;
        Bs[lcol + 2][lrow] = bv.z;
        Bs[lcol + 3][lrow] = bv.w;
        __syncthreads();
        #pragma unroll
        for (int kk = 0; kk < 16; kk++) {
            float4 a4 = *(const float4*)&As[kk][ty * 4];
            float4 b4 = *(const float4*)&Bs[kk][tx * 4];
            float av_[4] = {a4.x, a4.y, a4.z, a4.w};
            float bv_[4] = {b4.x, b4.y, b4.z, b4.w};
            #pragma unroll
            for (int i = 0; i < 4; i++)
                #pragma unroll
                for (int j = 0; j < 4; j++) acc[i][j] += av_[i] * bv_[j];
        }
        __syncthreads();
    }

    #pragma unroll
    for (int i = 0; i < 4; i++) {
        const int o = m0 + ty * 4 + i;
        const float bias = fcb[o];
        #pragma unroll
        for (int j = 0; j < 4; j++) {
            const int p = n0 + tx * 4 + j;
            const int b = p >> 14;                // / (256*64)
            const int n = (p >> 6) & 255;
            const int q = p & 63;
            const int row = ((n >> 4) << 3) + (q >> 3);
            const int col = ((n & 15) << 3) + (q & 7);
            out[(((size_t)b * CDIM + o) << 14) + (row << 7) + col] = acc[i][j] + bias;
        }
    }
}

// ============================================================================
// Fused halo attention: one CTA per (b, block, head). 256 threads.
// thread = q*4 + g;  each thread handles query q and key group g (49 keys).
// ============================================================================
#define ATT_SMEM_FLOATS (64*36 + 2*196*36 + 2*64*14 + 2*27*32)

__global__ __launch_bounds__(256) void halo_attn(const float* __restrict__ rel_h,
                                                 const float* __restrict__ rel_w) {
    extern __shared__ __align__(16) float sm[];
    float* qs  = sm;                 // [64][36]
    float* ks  = qs + 64 * 36;       // [196][36]
    float* vs  = ks + 196 * 36;      // [196][36]
    float* bwv = vs + 196 * 36;      // [64][14]
    float* bhv = bwv + 64 * 14;      // [64][14]
    float* rhs = bhv + 64 * 14;      // [27][32]
    float* rws = rhs + 27 * 32;      // [27][32]

    const int bid = blockIdx.x;
    const int h = bid & 7;
    const int n = (bid >> 3) & 255;
    const int b = bid >> 11;
    const int r0 = (n >> 4) << 3;    // block row origin
    const int c0 = (n & 15) << 3;    // block col origin
    const int tid = threadIdx.x;

    // ---- load q tile ----
    const float* qbase = g_q + ((size_t)b * CDIM + h * DHEAD) * NPIX;
    for (int idx = tid; idx < 64 * 32; idx += 256) {
        const int d = idx >> 6, q = idx & 63;
        const int row = r0 + (q >> 3), col = c0 + (q & 7);
        qs[q * 36 + d] = qbase[d * NPIX + row * WW + col];
    }
    // ---- load k/v window with zero halo padding ----
    const float* kbase = g_kv + ((size_t)b * 2 * CDIM + h * DHEAD) * NPIX;
    const float* vbase = kbase + (size_t)CDIM * NPIX;
    for (int idx = tid; idx < NKEY * 32; idx += 256) {
        const int d = idx / NKEY, kj = idx % NKEY;
        const int rr = r0 - HALO + kj / WINS;
        const int cc = c0 - HALO + kj % WINS;
        float kval = 0.f, vval = 0.f;
        if (rr >= 0 && rr < HH && cc >= 0 && cc < WW) {
            const int off = d * NPIX + rr * WW + cc;
            kval = kbase[off];
            vval = vbase[off];
        }
        ks[kj * 36 + d] = kval;
        vs[kj * 36 + d] = vval;
    }
    // ---- rel tables ----
    for (int idx = tid; idx < 27 * 32; idx += 256) {
        rhs[idx] = rel_h[idx];
        rws[idx] = rel_w[idx];
    }
    __syncthreads();

    // ---- per-query relative bias vectors ----
    for (int idx = tid; idx < 64 * WINS; idx += 256) {
        const int q = idx / WINS, j = idx % WINS;
        const int y = q & 7, x = q >> 3;
        const float* qrow = &qs[q * 36];
        const float* rw = &rws[(j - y + WINS - 1) * 32];
        const float* rh = &rhs[(j - x + WINS - 1) * 32];
        float sw = 0.f, sh = 0.f;
        #pragma unroll
        for (int d = 0; d < 32; d++) {
            sw += qrow[d] * rw[d];
            sh += qrow[d] * rh[d];
        }
        bwv[idx] = sw;   // bwv[q][j]
        bhv[idx] = sh;   // bhv[q][i]
    }
    __syncthreads();

    const int q = tid >> 2;
    const int g = tid & 3;

    float qreg[32];
    {
        const float4* q4 = (const float4*)(qs + q * 36);
        #pragma unroll
        for (int d4 = 0; d4 < 8; d4++) {
            float4 v = q4[d4];
            qreg[d4 * 4 + 0] = v.x; qreg[d4 * 4 + 1] = v.y;
            qreg[d4 * 4 + 2] = v.z; qreg[d4 * 4 + 3] = v.w;
        }
    }

    const float scale = 0.17677669529663687f;  // 1/sqrt(32)
    float sarr[49];
    #pragma unroll
    for (int t = 0; t < 49; t++) {
        const int k = g * 49 + t;
        const float4* k4 = (const float4*)(ks + k * 36);
        float a = 0.f;
        #pragma unroll
        for (int d4 = 0; d4 < 8; d4++) {
            float4 kv4 = k4[d4];
            a += qreg[d4 * 4 + 0] * kv4.x + qreg[d4 * 4 + 1] * kv4.y
               + qreg[d4 * 4 + 2] * kv4.z + qreg[d4 * 4 + 3] * kv4.w;
        }
        sarr[t] = a * scale + bwv[q * WINS + (k % WINS)] + bhv[q * WINS + (k / WINS)];
    }

    // ---- softmax across the 4 threads sharing this query ----
    float m = -1e30f;
    #pragma unroll
    for (int t = 0; t < 49; t++) m = fmaxf(m, sarr[t]);
    m = fmaxf(m, __shfl_xor_sync(0xffffffffu, m, 1));
    m = fmaxf(m, __shfl_xor_sync(0xffffffffu, m, 2));
    float sum = 0.f;
    #pragma unroll
    for (int t = 0; t < 49; t++) {
        sarr[t] = __expf(sarr[t] - m);
        sum += sarr[t];
    }
    sum += __shfl_xor_sync(0xffffffffu, sum, 1);
    sum += __shfl_xor_sync(0xffffffffu, sum, 2);
    const float inv = 1.f / sum;

    // ---- ctx = att @ v (partial over this thread's 49 keys) ----
    float acc[32];
    #pragma unroll
    for (int d = 0; d < 32; d++) acc[d] = 0.f;
    #pragma unroll
    for (int t = 0; t < 49; t++) {
        const float p = sarr[t];
        const float4* v4 = (const float4*)(vs + (g * 49 + t) * 36);
        #pragma unroll
        for (int d4 = 0; d4 < 8; d4++) {
            float4 vv = v4[d4];
            acc[d4 * 4 + 0] += p * vv.x;
            acc[d4 * 4 + 1] += p * vv.y;
            acc[d4 * 4 + 2] += p * vv.z;
            acc[d4 * 4 + 3] += p * vv.w;
        }
    }
    #pragma unroll
    for (int d = 0; d < 32; d++) {
        acc[d] += __shfl_xor_sync(0xffffffffu, acc[d], 1);
        acc[d] += __shfl_xor_sync(0xffffffffu, acc[d], 2);
    }

    if (g == 0) {
        float* cdst = g_ctx + (((size_t)(b * NBLK + n) * NQ + q) * CDIM + h * DHEAD);
        #pragma unroll
        for (int d4 = 0; d4 < 8; d4++) {
            ((float4*)cdst)[d4] = make_float4(acc[d4 * 4 + 0] * inv, acc[d4 * 4 + 1] * inv,
                                              acc[d4 * 4 + 2] * inv, acc[d4 * 4 + 3] * inv);
        }
    }
}

// ============================================================================
extern "C" void kernel_launch(void* const* d_in, const int* in_sizes, int n_in,
                              void* d_out, int out_size) {
    const float* x     = (const float*)d_in[0];
    const float* w_q   = (const float*)d_in[1];
    const float* w_kv  = (const float*)d_in[2];
    const float* fc_w  = (const float*)d_in[3];
    const float* fc_b  = (const float*)d_in[4];
    const float* rel_h = (const float*)d_in[5];
    const float* rel_w = (const float*)d_in[6];
    float* out = (float*)d_out;

    float *gq, *gkv;
    cudaGetSymbolAddress((void**)&gq, g_q);
    cudaGetSymbolAddress((void**)&gkv, g_kv);

    const int att_smem = ATT_SMEM_FLOATS * (int)sizeof(float);
    cudaFuncSetAttribute(halo_attn, cudaFuncAttributeMaxDynamicSharedMemorySize, att_smem);

    // q projection: M=256, N=16384, K=256
    gemm_nn<<<dim3(NPIX / 64, CDIM / 64, BATCH), 256>>>(w_q, x, gq, CDIM, NPIX, CDIM);
    // kv projection: M=512
    gemm_nn<<<dim3(NPIX / 64, (2 * CDIM) / 64, BATCH), 256>>>(w_kv, x, gkv, 2 * CDIM, NPIX, CDIM);
    // fused attention: one CTA per (b, block, head)
    halo_attn<<<BATCH * NBLK * HEADS, 256, att_smem>>>(rel_h, rel_w);
    // FC + bias + scatter to BCHW
    gemm_fc<<<dim3((BATCH * NBLK * NQ) / 64, CDIM / 64), 256>>>(fc_w, fc_b, out);
}

// round 5
// speedup vs baseline: 1.4244x; 1.4237x over previous
#include <cuda_runtime.h>
#include <cuda_bf16.h>
#include <cstdint>

#define BATCH 4
#define CDIM 256
#define HH 128
#define WW 128
#define NPIX (HH*WW)
#define HEADS 8
#define DHEAD 32
#define HALO 3
#define WINS 14
#define NBLK 256
#define NQ 64
#define NKEY 196
#define MTOT (BATCH*NPIX)

// ---- scratch ----
__device__ float g_xt [(size_t)MTOT * CDIM];
__device__ float g_qt [(size_t)MTOT * CDIM];
__device__ float g_kvt[(size_t)MTOT * 2 * CDIM];
__device__ float g_ctx[(size_t)MTOT * CDIM];

// ---------------- mma.sync helpers (baseline PTX, valid on compute_103) -----
__device__ __forceinline__ uint32_t smem_u32(const void* p) {
    uint32_t a;
    asm("{ .reg .u64 t; cvta.to.shared.u64 t, %1; cvt.u32.u64 %0, t; }" : "=r"(a) : "l"(p));
    return a;
}
__device__ __forceinline__ void ldm_x4(uint32_t& r0, uint32_t& r1, uint32_t& r2, uint32_t& r3,
                                       uint32_t addr) {
    asm volatile("ldmatrix.sync.aligned.m8n8.x4.shared.b16 {%0,%1,%2,%3}, [%4];"
                 : "=r"(r0), "=r"(r1), "=r"(r2), "=r"(r3) : "r"(addr));
}
__device__ __forceinline__ void ldm_x2(uint32_t& r0, uint32_t& r1, uint32_t addr) {
    asm volatile("ldmatrix.sync.aligned.m8n8.x2.shared.b16 {%0,%1}, [%2];"
                 : "=r"(r0), "=r"(r1) : "r"(addr));
}
__device__ __forceinline__ void mma_bf16(float& d0, float& d1, float& d2, float& d3,
                                         uint32_t a0, uint32_t a1, uint32_t a2, uint32_t a3,
                                         uint32_t b0, uint32_t b1) {
    asm volatile("mma.sync.aligned.m16n8k16.row.col.f32.bf16.bf16.f32 "
                 "{%0,%1,%2,%3}, {%4,%5,%6,%7}, {%8,%9}, {%0,%1,%2,%3};"
                 : "+f"(d0), "+f"(d1), "+f"(d2), "+f"(d3)
                 : "r"(a0), "r"(a1), "r"(a2), "r"(a3), "r"(b0), "r"(b1));
}

// ============================================================================
// x[b][c][p] -> x_t[(b,p)][c]
// ============================================================================
__global__ __launch_bounds__(256) void transpose_x(const float* __restrict__ x) {
    __shared__ float t[32][33];
    const int b = blockIdx.z, c0 = blockIdx.y * 32, p0 = blockIdx.x * 32;
    const int tx = threadIdx.x, ty = threadIdx.y;
    const float* src = x + (size_t)b * CDIM * NPIX;
    #pragma unroll
    for (int i = ty; i < 32; i += 8)
        t[i][tx] = src[(size_t)(c0 + i) * NPIX + p0 + tx];
    __syncthreads();
    #pragma unroll
    for (int i = ty; i < 32; i += 8)
        g_xt[((size_t)b * NPIX + p0 + i) * CDIM + c0 + tx] = t[tx][i];
}

// ============================================================================
// TN GEMM via mma.sync bf16 3-term: D[m][n] = sum_k A[m][k]*B[n][k], K=256.
// CTA tile 128x128, 8 warps (2x4), warp tile 64x32, KC=32 per stage.
// smem rows padded to 40 bf16 (80 B) for conflict-free ldmatrix.
// mode 0: C row-major (ldc). mode 1: +bias, scatter to BCHW out.
// ============================================================================
#define LROW 40

__global__ __launch_bounds__(256) void gemm_mma(const float* __restrict__ A,
                                                const float* __restrict__ Bw,
                                                float* __restrict__ C, int ldc, int mode,
                                                const float* __restrict__ fcb,
                                                float* __restrict__ out) {
    __shared__ __align__(16) __nv_bfloat16 sAh[128 * LROW];
    __shared__ __align__(16) __nv_bfloat16 sAl[128 * LROW];
    __shared__ __align__(16) __nv_bfloat16 sBh[128 * LROW];
    __shared__ __align__(16) __nv_bfloat16 sBl[128 * LROW];

    const int tid = threadIdx.x, wid = tid >> 5, lane = tid & 31;
    const int wm = wid >> 2, wn = wid & 3;          // warp grid 2x4
    const size_t m0 = (size_t)blockIdx.x * 128;
    const size_t n0 = (size_t)blockIdx.y * 128;

    const uint32_t uAh = smem_u32(sAh), uAl = smem_u32(sAl);
    const uint32_t uBh = smem_u32(sBh), uBl = smem_u32(sBl);

    // fill task: 1024 cells (mat x 128 rows x 4 cells of 8 floats); 4 per thread
    const int f_mat  = tid >> 7;            // covers ids via +256*r below
    float acc[4][4][4];
    #pragma unroll
    for (int a = 0; a < 4; a++)
        #pragma unroll
        for (int b = 0; b < 4; b++)
            #pragma unroll
            for (int c = 0; c < 4; c++) acc[a][b][c] = 0.f;

    const int i8 = lane & 7, g = lane >> 3;
    // A-ldmatrix lane geometry
    const int a_r = wm * 64 + ((g & 1) << 3) + i8;
    const int a_c = (g >> 1) << 3;
    // B-ldmatrix lane geometry (.x2: lanes 0-15 used; give all lanes valid addrs)
    const int b_r = wn * 32 + i8;
    const int b_sel = (lane >> 3) & 1;

    for (int it = 0; it < 8; it++) {
        if (it) __syncthreads();
        #pragma unroll
        for (int r = 0; r < 4; r++) {
            const int id = tid + 256 * r;
            const int mat = id >> 9;
            const int row = (id >> 2) & 127;
            const int cell = id & 3;
            const float* src = (mat ? (Bw + (n0 + row) * CDIM) : (A + (m0 + row) * CDIM))
                               + it * 32 + cell * 8;
            const float4 v0 = *(const float4*)src;
            const float4 v1 = *(const float4*)(src + 4);
            const float f[8] = {v0.x, v0.y, v0.z, v0.w, v1.x, v1.y, v1.z, v1.w};
            uint32_t hi[4], lo[4];
            #pragma unroll
            for (int j = 0; j < 4; j++) {
                const float a = f[2 * j], b = f[2 * j + 1];
                __nv_bfloat162 h2, l2;
                h2.x = __float2bfloat16_rn(a);
                h2.y = __float2bfloat16_rn(b);
                l2.x = __float2bfloat16_rn(a - __bfloat162float(h2.x));
                l2.y = __float2bfloat16_rn(b - __bfloat162float(h2.y));
                hi[j] = *(uint32_t*)&h2;
                lo[j] = *(uint32_t*)&l2;
            }
            __nv_bfloat16* dh = (mat ? sBh : sAh) + row * LROW + cell * 8;
            __nv_bfloat16* dl = (mat ? sBl : sAl) + row * LROW + cell * 8;
            *(uint4*)dh = make_uint4(hi[0], hi[1], hi[2], hi[3]);
            *(uint4*)dl = make_uint4(lo[0], lo[1], lo[2], lo[3]);
        }
        __syncthreads();

        #pragma unroll
        for (int ks = 0; ks < 2; ks++) {
            const int kb = ks * 16;
            uint32_t ah[4][4], al[4][4];
            #pragma unroll
            for (int ms = 0; ms < 4; ms++) {
                const uint32_t off = ((a_r + ms * 16) * LROW + kb + a_c) * 2;
                ldm_x4(ah[ms][0], ah[ms][1], ah[ms][2], ah[ms][3], uAh + off);
                ldm_x4(al[ms][0], al[ms][1], al[ms][2], al[ms][3], uAl + off);
            }
            #pragma unroll
            for (int ns = 0; ns < 4; ns++) {
                const uint32_t boff = ((b_r + ns * 8) * LROW + kb + b_sel * 8) * 2;
                uint32_t bh0, bh1, bl0, bl1;
                ldm_x2(bh0, bh1, uBh + boff);
                ldm_x2(bl0, bl1, uBl + boff);
                #pragma unroll
                for (int ms = 0; ms < 4; ms++) {
                    float* d = acc[ms][ns];
                    mma_bf16(d[0], d[1], d[2], d[3],
                             ah[ms][0], ah[ms][1], ah[ms][2], ah[ms][3], bh0, bh1);
                    mma_bf16(d[0], d[1], d[2], d[3],
                             ah[ms][0], ah[ms][1], ah[ms][2], ah[ms][3], bl0, bl1);
                    mma_bf16(d[0], d[1], d[2], d[3],
                             al[ms][0], al[ms][1], al[ms][2], al[ms][3], bh0, bh1);
                }
            }
        }
    }

    // ---- epilogue ----
    const int er = lane >> 2, ec = (lane & 3) * 2;
    #pragma unroll
    for (int ms = 0; ms < 4; ms++) {
        #pragma unroll
        for (int ns = 0; ns < 4; ns++) {
            const float* d = acc[ms][ns];
            const size_t m = m0 + wm * 64 + ms * 16 + er;
            const int nl = (int)n0 + wn * 32 + ns * 8 + ec;
            if (mode == 0) {
                *(float2*)&C[m * ldc + nl] = make_float2(d[0], d[1]);
                *(float2*)&C[(m + 8) * ldc + nl] = make_float2(d[2], d[3]);
            } else {
                #pragma unroll
                for (int rr = 0; rr < 2; rr++) {
                    const size_t mm = m + rr * 8;
                    const int b = (int)(mm >> 14), n = (int)((mm >> 6) & 255), q = (int)(mm & 63);
                    const int orow = ((n >> 4) << 3) + (q >> 3);
                    const int ocol = ((n & 15) << 3) + (q & 7);
                    const size_t base = (((size_t)b * CDIM) << 14) + (orow << 7) + ocol;
                    out[base + ((size_t)nl << 14)]       = d[rr * 2]     + fcb[nl];
                    out[base + ((size_t)(nl + 1) << 14)] = d[rr * 2 + 1] + fcb[nl + 1];
                }
            }
        }
    }
}

// ============================================================================
// Fused halo attention, register-tiled FFMA. One CTA per (b, block, head).
// ============================================================================
#define ATT_SMEM_FLOATS (196 * 36 + 12800)

__global__ __launch_bounds__(256, 2) void halo_attn(const float* __restrict__ rel_h,
                                                    const float* __restrict__ rel_w) {
    extern __shared__ __align__(16) float sm[];
    float* vs  = sm;              // [196][36]
    float* rg2 = sm + 196 * 36;
    float* qs  = rg2;             // [32][64] d-major
    float* ks  = rg2 + 2048;      // [32][224] d-major, zero-padded keys
    float* bwv = rg2 + 9216;      // [64][14]
    float* bhv = rg2 + 10112;     // [64][14]
    float* rhs = rg2 + 11008;     // [27][32]
    float* rws = rg2 + 11872;     // [27][32]
    float* att = rg2;             // [64][200] aliased after sync

    const int bid = blockIdx.x;
    const int h = bid & 7;
    const int n = (bid >> 3) & 255;
    const int b = bid >> 11;
    const int r0 = (n >> 4) << 3;
    const int c0 = (n & 15) << 3;
    const int tid = threadIdx.x;

    const float* qrows = g_qt + (size_t)b * NPIX * CDIM;
    #pragma unroll
    for (int it = 0; it < 2; it++) {
        const int id = tid + it * 256;
        const int q = id & 63, d4 = id >> 6;
        const int pix = (r0 + (q >> 3)) * WW + c0 + (q & 7);
        float4 v = *(const float4*)&qrows[(size_t)pix * CDIM + h * DHEAD + d4 * 4];
        qs[(d4 * 4 + 0) * 64 + q] = v.x;
        qs[(d4 * 4 + 1) * 64 + q] = v.y;
        qs[(d4 * 4 + 2) * 64 + q] = v.z;
        qs[(d4 * 4 + 3) * 64 + q] = v.w;
    }
    const float* kvrows = g_kvt + (size_t)b * NPIX * (2 * CDIM);
    for (int idx = tid; idx < NKEY * 16; idx += 256) {
        const int kj = idx >> 4, d4 = idx & 15;
        const int rr = r0 - HALO + kj / WINS;
        const int cc = c0 - HALO + kj % WINS;
        float4 v = make_float4(0.f, 0.f, 0.f, 0.f);
        if (rr >= 0 && rr < HH && cc >= 0 && cc < WW) {
            const size_t pr = (size_t)(rr * WW + cc) * (2 * CDIM);
            const int col = (d4 < 8) ? (h * DHEAD + d4 * 4) : (CDIM + h * DHEAD + (d4 - 8) * 4);
            v = *(const float4*)&kvrows[pr + col];
        }
        if (d4 < 8) {
            ks[(d4 * 4 + 0) * 224 + kj] = v.x;
            ks[(d4 * 4 + 1) * 224 + kj] = v.y;
            ks[(d4 * 4 + 2) * 224 + kj] = v.z;
            ks[(d4 * 4 + 3) * 224 + kj] = v.w;
        } else {
            *(float4*)&vs[kj * 36 + (d4 - 8) * 4] = v;
        }
    }
    for (int idx = tid; idx < 32 * 28; idx += 256)
        ks[(idx / 28) * 224 + 196 + (idx % 28)] = 0.f;
    for (int idx = tid; idx < 27 * 32; idx += 256) {
        rhs[idx] = rel_h[idx];
        rws[idx] = rel_w[idx];
    }
    __syncthreads();

    for (int idx = tid; idx < 64 * WINS; idx += 256) {
        const int q = idx / WINS, j = idx % WINS;
        const int y = q & 7, x = q >> 3;
        const float* rw = &rws[(j - y + WINS - 1) * 32];
        const float* rh = &rhs[(j - x + WINS - 1) * 32];
        float sw = 0.f, sh = 0.f;
        #pragma unroll
        for (int d = 0; d < 32; d++) {
            const float qv = qs[d * 64 + q];
            sw += qv * rw[d];
            sh += qv * rh[d];
        }
        bwv[idx] = sw;
        bhv[idx] = sh;
    }
    __syncthreads();

    const int w = tid >> 5, lane = tid & 31;
    float s[8][7];
    #pragma unroll
    for (int i = 0; i < 8; i++)
        #pragma unroll
        for (int j = 0; j < 7; j++) s[i][j] = 0.f;

    #pragma unroll 4
    for (int d = 0; d < 32; d++) {
        const float4 qa = *(const float4*)&qs[d * 64 + w * 8];
        const float4 qb = *(const float4*)&qs[d * 64 + w * 8 + 4];
        float kv[7];
        #pragma unroll
        for (int j = 0; j < 7; j++) kv[j] = ks[d * 224 + lane + 32 * j];
        const float qv[8] = {qa.x, qa.y, qa.z, qa.w, qb.x, qb.y, qb.z, qb.w};
        #pragma unroll
        for (int i = 0; i < 8; i++)
            #pragma unroll
            for (int j = 0; j < 7; j++) s[i][j] += qv[i] * kv[j];
    }

    const float scale = 0.17677669529663687f;
    #pragma unroll
    for (int j = 0; j < 7; j++) {
        const int k = lane + 32 * j;
        const bool valid = (k < NKEY);
        const int km = k % WINS, kd = k / WINS;
        #pragma unroll
        for (int i = 0; i < 8; i++) {
            const int q = w * 8 + i;
            s[i][j] = valid ? (s[i][j] * scale + bwv[q * WINS + km] + bhv[q * WINS + kd]) : -1e30f;
        }
    }

    float inv[8];
    #pragma unroll
    for (int i = 0; i < 8; i++) {
        float m = -1e30f;
        #pragma unroll
        for (int j = 0; j < 7; j++) m = fmaxf(m, s[i][j]);
        #pragma unroll
        for (int o = 16; o > 0; o >>= 1) m = fmaxf(m, __shfl_xor_sync(0xffffffffu, m, o));
        float sum = 0.f;
        #pragma unroll
        for (int j = 0; j < 7; j++) {
            s[i][j] = __expf(s[i][j] - m);
            sum += s[i][j];
        }
        #pragma unroll
        for (int o = 16; o > 0; o >>= 1) sum += __shfl_xor_sync(0xffffffffu, sum, o);
        inv[i] = 1.f / sum;
    }

    __syncthreads();
    #pragma unroll
    for (int i = 0; i < 8; i++)
        #pragma unroll
        for (int j = 0; j < 7; j++) {
            const int k = lane + 32 * j;
            if (k < NKEY) att[(w * 8 + i) * 200 + k] = s[i][j] * inv[i];
        }
    __syncthreads();

    const int qg = tid >> 3, dg = tid & 7;
    const int q0 = qg * 2;
    float a00 = 0.f, a01 = 0.f, a02 = 0.f, a03 = 0.f;
    float a10 = 0.f, a11 = 0.f, a12 = 0.f, a13 = 0.f;
    #pragma unroll 4
    for (int k = 0; k < NKEY; k++) {
        const float p0 = att[q0 * 200 + k];
        const float p1 = att[(q0 + 1) * 200 + k];
        const float4 vv = *(const float4*)&vs[k * 36 + dg * 4];
        a00 += p0 * vv.x; a01 += p0 * vv.y; a02 += p0 * vv.z; a03 += p0 * vv.w;
        a10 += p1 * vv.x; a11 += p1 * vv.y; a12 += p1 * vv.z; a13 += p1 * vv.w;
    }
    float* cdst = g_ctx + (((size_t)(b * NBLK + n) * NQ + q0) * CDIM + h * DHEAD + dg * 4);
    *(float4*)cdst = make_float4(a00, a01, a02, a03);
    *(float4*)(cdst + CDIM) = make_float4(a10, a11, a12, a13);
}

// ============================================================================
extern "C" void kernel_launch(void* const* d_in, const int* in_sizes, int n_in,
                              void* d_out, int out_size) {
    const float* x     = (const float*)d_in[0];
    const float* w_q   = (const float*)d_in[1];
    const float* w_kv  = (const float*)d_in[2];
    const float* fc_w  = (const float*)d_in[3];
    const float* fc_b  = (const float*)d_in[4];
    const float* rel_h = (const float*)d_in[5];
    const float* rel_w = (const float*)d_in[6];
    float* out = (float*)d_out;

    float *xt, *qt, *kvt, *ctx;
    cudaGetSymbolAddress((void**)&xt, g_xt);
    cudaGetSymbolAddress((void**)&qt, g_qt);
    cudaGetSymbolAddress((void**)&kvt, g_kvt);
    cudaGetSymbolAddress((void**)&ctx, g_ctx);

    const int att_smem = ATT_SMEM_FLOATS * (int)sizeof(float);
    cudaFuncSetAttribute(halo_attn, cudaFuncAttributeMaxDynamicSharedMemorySize, att_smem);

    transpose_x<<<dim3(NPIX / 32, CDIM / 32, BATCH), dim3(32, 8)>>>(x);
    gemm_mma<<<dim3(MTOT / 128, 2), 256>>>(xt, w_q, qt, CDIM, 0, nullptr, nullptr);
    gemm_mma<<<dim3(MTOT / 128, 4), 256>>>(xt, w_kv, kvt, 2 * CDIM, 0, nullptr, nullptr);
    halo_attn<<<BATCH * NBLK * HEADS, 256, att_smem>>>(rel_h, rel_w);
    gemm_mma<<<dim3(MTOT / 128, 2), 256>>>(ctx, fc_w, nullptr, 0, 1, fc_b, out);
}

// round 6
// speedup vs baseline: 1.9883x; 1.3959x over previous
#include <cuda_runtime.h>
#include <cuda_bf16.h>
#include <cstdint>

#define BATCH 4
#define CDIM 256
#define HH 128
#define WW 128
#define NPIX (HH*WW)
#define HEADS 8
#define DHEAD 32
#define HALO 3
#define WINS 14
#define NBLK 256
#define NQ 64
#define NKEY 196
#define MTOT (BATCH*NPIX)
#define SCALE 0.17677669529663687f

// ---- scratch: bf16 hi/lo pairs everywhere ----
__device__ __nv_bfloat16 g_xh [(size_t)MTOT * CDIM];
__device__ __nv_bfloat16 g_xl [(size_t)MTOT * CDIM];
__device__ __nv_bfloat16 g_qh [(size_t)MTOT * CDIM];
__device__ __nv_bfloat16 g_ql [(size_t)MTOT * CDIM];
__device__ __nv_bfloat16 g_kvh[(size_t)MTOT * 2 * CDIM];
__device__ __nv_bfloat16 g_kvl[(size_t)MTOT * 2 * CDIM];
__device__ __nv_bfloat16 g_ch [(size_t)MTOT * CDIM];
__device__ __nv_bfloat16 g_cl [(size_t)MTOT * CDIM];
__device__ __nv_bfloat16 g_wh [(size_t)1024 * CDIM];
__device__ __nv_bfloat16 g_wl [(size_t)1024 * CDIM];

// ---------------- mma.sync helpers (baseline PTX, valid on compute_103) -----
__device__ __forceinline__ uint32_t smem_u32(const void* p) {
    uint32_t a;
    asm("{ .reg .u64 t; cvta.to.shared.u64 t, %1; cvt.u32.u64 %0, t; }" : "=r"(a) : "l"(p));
    return a;
}
__device__ __forceinline__ void ldm_x4(uint32_t& r0, uint32_t& r1, uint32_t& r2, uint32_t& r3,
                                       uint32_t addr) {
    asm volatile("ldmatrix.sync.aligned.m8n8.x4.shared.b16 {%0,%1,%2,%3}, [%4];"
                 : "=r"(r0), "=r"(r1), "=r"(r2), "=r"(r3) : "r"(addr));
}
__device__ __forceinline__ void ldm_x4t(uint32_t& r0, uint32_t& r1, uint32_t& r2, uint32_t& r3,
                                        uint32_t addr) {
    asm volatile("ldmatrix.sync.aligned.m8n8.x4.trans.shared.b16 {%0,%1,%2,%3}, [%4];"
                 : "=r"(r0), "=r"(r1), "=r"(r2), "=r"(r3) : "r"(addr));
}
__device__ __forceinline__ void mma_bf16(float* d,
                                         uint32_t a0, uint32_t a1, uint32_t a2, uint32_t a3,
                                         uint32_t b0, uint32_t b1) {
    asm volatile("mma.sync.aligned.m16n8k16.row.col.f32.bf16.bf16.f32 "
                 "{%0,%1,%2,%3}, {%4,%5,%6,%7}, {%8,%9}, {%0,%1,%2,%3};"
                 : "+f"(d[0]), "+f"(d[1]), "+f"(d[2]), "+f"(d[3])
                 : "r"(a0), "r"(a1), "r"(a2), "r"(a3), "r"(b0), "r"(b1));
}
__device__ __forceinline__ void split2(float x, float y, uint32_t& hi, uint32_t& lo) {
    __nv_bfloat162 h2, l2;
    h2.x = __float2bfloat16_rn(x);
    h2.y = __float2bfloat16_rn(y);
    l2.x = __float2bfloat16_rn(x - __bfloat162float(h2.x));
    l2.y = __float2bfloat16_rn(y - __bfloat162float(h2.y));
    hi = *(uint32_t*)&h2;
    lo = *(uint32_t*)&l2;
}

// ============================================================================
// x[b][c][p] -> x_t[(b,p)][c] split to bf16 hi/lo
// ============================================================================
__global__ __launch_bounds__(256) void transpose_x(const float* __restrict__ x) {
    __shared__ float t[32][33];
    const int b = blockIdx.z, c0 = blockIdx.y * 32, p0 = blockIdx.x * 32;
    const int tx = threadIdx.x, ty = threadIdx.y;
    const float* src = x + (size_t)b * CDIM * NPIX;
    #pragma unroll
    for (int i = ty; i < 32; i += 8)
        t[i][tx] = src[(size_t)(c0 + i) * NPIX + p0 + tx];
    __syncthreads();
    #pragma unroll
    for (int i = ty; i < 32; i += 8) {
        const float v = t[tx][i];
        const size_t o = ((size_t)b * NPIX + p0 + i) * CDIM + c0 + tx;
        const __nv_bfloat16 h = __float2bfloat16_rn(v);
        g_xh[o] = h;
        g_xl[o] = __float2bfloat16_rn(v - __bfloat162float(h));
    }
}

// ============================================================================
// weights -> g_wh/g_wl (wq rows 0-255, wkv 256-767, fc 768-1023)
// ============================================================================
__global__ __launch_bounds__(256) void split_w(const float* __restrict__ wq,
                                               const float* __restrict__ wkv,
                                               const float* __restrict__ fcw) {
    const int idx = blockIdx.x * 256 + threadIdx.x;   // 0 .. 1024*256-1
    const int r = idx >> 8, c = idx & 255;
    float v;
    if (r < 256) v = wq[r * 256 + c];
    else if (r < 768) v = wkv[(r - 256) * 256 + c];
    else v = fcw[(r - 768) * 256 + c];
    const __nv_bfloat16 h = __float2bfloat16_rn(v);
    g_wh[idx] = h;
    g_wl[idx] = __float2bfloat16_rn(v - __bfloat162float(h));
}

// ============================================================================
// TN GEMM via mma.sync bf16 3-term, pre-split inputs. Tile 128x128, K=256.
// mode 0: write bf16 hi/lo to Ch/Cl. mode 1: fp32 +bias, scatter to BCHW out.
// ============================================================================
#define LROW 40

__global__ __launch_bounds__(256) void gemm_mma(const __nv_bfloat16* __restrict__ Ah,
                                                const __nv_bfloat16* __restrict__ Al,
                                                const __nv_bfloat16* __restrict__ Bh,
                                                const __nv_bfloat16* __restrict__ Bl,
                                                __nv_bfloat16* __restrict__ Ch,
                                                __nv_bfloat16* __restrict__ Cl,
                                                int ldc, int mode,
                                                const float* __restrict__ fcb,
                                                float* __restrict__ out) {
    __shared__ __align__(16) __nv_bfloat16 sAh[128 * LROW];
    __shared__ __align__(16) __nv_bfloat16 sAl[128 * LROW];
    __shared__ __align__(16) __nv_bfloat16 sBh[128 * LROW];
    __shared__ __align__(16) __nv_bfloat16 sBl[128 * LROW];

    const int tid = threadIdx.x, wid = tid >> 5, lane = tid & 31;
    const int wm = wid >> 2, wn = wid & 3;
    const size_t m0 = (size_t)blockIdx.x * 128;
    const size_t n0 = (size_t)blockIdx.y * 128;

    const uint32_t uAh = smem_u32(sAh), uAl = smem_u32(sAl);
    const uint32_t uBh = smem_u32(sBh), uBl = smem_u32(sBl);

    float acc[4][4][4];
    #pragma unroll
    for (int a = 0; a < 4; a++)
        #pragma unroll
        for (int b = 0; b < 4; b++)
            #pragma unroll
            for (int c = 0; c < 4; c++) acc[a][b][c] = 0.f;

    const int i8 = lane & 7, g = lane >> 3;
    const int a_r = wm * 64 + ((g & 1) << 3) + i8;
    const int a_c = (g >> 1) << 3;
    const int b_r = wn * 32 + i8;
    const int b_sel = (lane >> 3) & 1;

    for (int it = 0; it < 8; it++) {
        if (it) __syncthreads();
        #pragma unroll
        for (int r = 0; r < 4; r++) {
            const int id = tid + 256 * r;
            const int mat = id >> 9;
            const int row = (id >> 2) & 127;
            const int cell = id & 3;
            const size_t off = ((mat ? n0 : m0) + row) * CDIM + it * 32 + cell * 8;
            const uint4 vh = *(const uint4*)((mat ? Bh : Ah) + off);
            const uint4 vl = *(const uint4*)((mat ? Bl : Al) + off);
            __nv_bfloat16* dh = (mat ? sBh : sAh) + row * LROW + cell * 8;
            __nv_bfloat16* dl = (mat ? sBl : sAl) + row * LROW + cell * 8;
            *(uint4*)dh = vh;
            *(uint4*)dl = vl;
        }
        __syncthreads();

        #pragma unroll
        for (int ks = 0; ks < 2; ks++) {
            const int kb = ks * 16;
            uint32_t ah[4][4], al[4][4];
            #pragma unroll
            for (int ms = 0; ms < 4; ms++) {
                const uint32_t off = ((a_r + ms * 16) * LROW + kb + a_c) * 2;
                ldm_x4(ah[ms][0], ah[ms][1], ah[ms][2], ah[ms][3], uAh + off);
                ldm_x4(al[ms][0], al[ms][1], al[ms][2], al[ms][3], uAl + off);
            }
            #pragma unroll
            for (int ns = 0; ns < 4; ns++) {
                const uint32_t boff = ((b_r + ns * 8) * LROW + kb + b_sel * 8) * 2;
                uint32_t bh0, bh1, bl0, bl1;
                asm volatile("ldmatrix.sync.aligned.m8n8.x2.shared.b16 {%0,%1}, [%2];"
                             : "=r"(bh0), "=r"(bh1) : "r"(uBh + boff));
                asm volatile("ldmatrix.sync.aligned.m8n8.x2.shared.b16 {%0,%1}, [%2];"
                             : "=r"(bl0), "=r"(bl1) : "r"(uBl + boff));
                #pragma unroll
                for (int ms = 0; ms < 4; ms++) {
                    mma_bf16(acc[ms][ns], ah[ms][0], ah[ms][1], ah[ms][2], ah[ms][3], bh0, bh1);
                    mma_bf16(acc[ms][ns], ah[ms][0], ah[ms][1], ah[ms][2], ah[ms][3], bl0, bl1);
                    mma_bf16(acc[ms][ns], al[ms][0], al[ms][1], al[ms][2], al[ms][3], bh0, bh1);
                }
            }
        }
    }

    const int er = lane >> 2, ec = (lane & 3) * 2;
    #pragma unroll
    for (int ms = 0; ms < 4; ms++) {
        #pragma unroll
        for (int ns = 0; ns < 4; ns++) {
            const float* d = acc[ms][ns];
            const size_t m = m0 + wm * 64 + ms * 16 + er;
            const int nl = (int)n0 + wn * 32 + ns * 8 + ec;
            if (mode == 0) {
                #pragma unroll
                for (int rr = 0; rr < 2; rr++) {
                    uint32_t hi, lo;
                    split2(d[rr * 2], d[rr * 2 + 1], hi, lo);
                    *(uint32_t*)&Ch[(m + rr * 8) * ldc + nl] = hi;
                    *(uint32_t*)&Cl[(m + rr * 8) * ldc + nl] = lo;
                }
            } else {
                #pragma unroll
                for (int rr = 0; rr < 2; rr++) {
                    const size_t mm = m + rr * 8;
                    const int b = (int)(mm >> 14), n = (int)((mm >> 6) & 255), q = (int)(mm & 63);
                    const int orow = ((n >> 4) << 3) + (q >> 3);
                    const int ocol = ((n & 15) << 3) + (q & 7);
                    const size_t base = (((size_t)b * CDIM) << 14) + (orow << 7) + ocol;
                    out[base + ((size_t)nl << 14)]       = d[rr * 2]     + fcb[nl];
                    out[base + ((size_t)(nl + 1) << 14)] = d[rr * 2 + 1] + fcb[nl + 1];
                }
            }
        }
    }
}

// ============================================================================
// MMA halo attention. One CTA per (b, block, head), 256 threads = 8 warps.
// pair p = w>>1 handles queries 16p..16p+15; half hf = w&1 keys 112hf..+111.
// ============================================================================
#define ATT_SMEM 105216

__global__ __launch_bounds__(256, 2) void halo_attn(const float* __restrict__ rel_h,
                                                    const float* __restrict__ rel_w) {
    extern __shared__ __align__(16) char smx[];
    __nv_bfloat16* sQh = (__nv_bfloat16*)(smx);            // [64][40]
    __nv_bfloat16* sQl = (__nv_bfloat16*)(smx + 5120);
    __nv_bfloat16* sKh = (__nv_bfloat16*)(smx + 10240);    // [224][40]
    __nv_bfloat16* sKl = (__nv_bfloat16*)(smx + 28160);
    __nv_bfloat16* sVh = (__nv_bfloat16*)(smx + 46080);    // [224][40] key-major
    __nv_bfloat16* sVl = (__nv_bfloat16*)(smx + 64000);
    float* bwv  = (float*)(smx + 81920);                   // [64][14]
    float* bhv  = (float*)(smx + 85504);
    float* rhs  = (float*)(smx + 89088);                   // [27][32]
    float* rws  = (float*)(smx + 92544);
    float* redm = (float*)(smx + 96000);                   // [4][2][16]
    float* reds = (float*)(smx + 96512);
    float* ctxb = (float*)(smx + 97024);                   // [64][32]

    const int bid = blockIdx.x;
    const int h = bid & 7;
    const int n = (bid >> 3) & 255;
    const int b = bid >> 11;
    const int r0 = (n >> 4) << 3;
    const int c0 = (n & 15) << 3;
    const int tid = threadIdx.x;

    // ---- load Q (64 rows x 4 cells of 8 bf16) ----
    {
        const int row = tid >> 2, cell = tid & 3;
        const int pix = (r0 + (row >> 3)) * WW + c0 + (row & 7);
        const size_t gr = ((size_t)b * NPIX + pix) * CDIM + h * DHEAD + cell * 8;
        *(uint4*)(sQh + row * 40 + cell * 8) = *(const uint4*)(g_qh + gr);
        *(uint4*)(sQl + row * 40 + cell * 8) = *(const uint4*)(g_ql + gr);
    }
    // ---- load K/V windows (224 rows x 4 cells x {k,v}), zero pads ----
    for (int t = tid; t < 1792; t += 256) {
        const int kj = t >> 3, rem = t & 7;
        const int mat = rem >> 2, cell = rem & 3;
        const int rr = r0 - HALO + kj / WINS;
        const int cc = c0 - HALO + kj % WINS;
        uint4 vh = make_uint4(0, 0, 0, 0), vl = vh;
        if (kj < NKEY && rr >= 0 && rr < HH && cc >= 0 && cc < WW) {
            const size_t off = ((size_t)b * NPIX + rr * WW + cc) * (2 * CDIM)
                             + (mat ? CDIM : 0) + h * DHEAD + cell * 8;
            vh = *(const uint4*)(g_kvh + off);
            vl = *(const uint4*)(g_kvl + off);
        }
        __nv_bfloat16* dh = (mat ? sVh : sKh) + kj * 40 + cell * 8;
        __nv_bfloat16* dl = (mat ? sVl : sKl) + kj * 40 + cell * 8;
        *(uint4*)dh = vh;
        *(uint4*)dl = vl;
    }
    for (int t = tid; t < 27 * 32; t += 256) {
        rhs[t] = rel_h[t];
        rws[t] = rel_w[t];
    }
    __syncthreads();

    // ---- per-query bias tables ----
    for (int t = tid; t < 64 * WINS; t += 256) {
        const int q = t / WINS, j = t % WINS;
        const int y = q & 7, x = q >> 3;
        const float* rw = &rws[(j - y + WINS - 1) * 32];
        const float* rh = &rhs[(j - x + WINS - 1) * 32];
        float sw = 0.f, sh = 0.f;
        #pragma unroll
        for (int d = 0; d < 32; d++) {
            const float qv = __bfloat162float(sQh[q * 40 + d]) + __bfloat162float(sQl[q * 40 + d]);
            sw += qv * rw[d];
            sh += qv * rh[d];
        }
        bwv[t] = sw;
        bhv[t] = sh;
    }
    __syncthreads();

    const int w = tid >> 5, lane = tid & 31;
    const int p = w >> 1, hf = w & 1;
    const int q0 = p * 16, kb0 = hf * 112;
    const int gid = lane >> 2, tg = lane & 3;
    const int i8 = lane & 7;

    const uint32_t uQh = smem_u32(sQh), uQl = smem_u32(sQl);
    const uint32_t uKh = smem_u32(sKh), uKl = smem_u32(sKl);
    const uint32_t uVh = smem_u32(sVh), uVl = smem_u32(sVl);

    // ---- score MMAs: sc[14 n-blocks][4] ----
    float sc[14][4];
    #pragma unroll
    for (int nb = 0; nb < 14; nb++)
        #pragma unroll
        for (int c = 0; c < 4; c++) sc[nb][c] = 0.f;

    const int a_row = q0 + (((lane >> 3) & 1) << 3) + i8;
    const int a_col = (lane >> 4) << 3;
    const int k_rowoff = ((lane >> 4) << 3) + i8;
    const int k_col = ((lane >> 3) & 1) << 3;

    #pragma unroll
    for (int ks = 0; ks < 2; ks++) {
        uint32_t ah[4], al[4];
        const uint32_t aoff = (a_row * 40 + ks * 16 + a_col) * 2;
        ldm_x4(ah[0], ah[1], ah[2], ah[3], uQh + aoff);
        ldm_x4(al[0], al[1], al[2], al[3], uQl + aoff);
        #pragma unroll
        for (int kb2 = 0; kb2 < 7; kb2++) {
            const uint32_t koff = ((kb0 + kb2 * 16 + k_rowoff) * 40 + ks * 16 + k_col) * 2;
            uint32_t bh0, bh1, bh2, bh3, bl0, bl1, bl2, bl3;
            ldm_x4(bh0, bh1, bh2, bh3, uKh + koff);
            ldm_x4(bl0, bl1, bl2, bl3, uKl + koff);
            mma_bf16(sc[2 * kb2], ah[0], ah[1], ah[2], ah[3], bh0, bh1);
            mma_bf16(sc[2 * kb2], ah[0], ah[1], ah[2], ah[3], bl0, bl1);
            mma_bf16(sc[2 * kb2], al[0], al[1], al[2], al[3], bh0, bh1);
            mma_bf16(sc[2 * kb2 + 1], ah[0], ah[1], ah[2], ah[3], bh2, bh3);
            mma_bf16(sc[2 * kb2 + 1], ah[0], ah[1], ah[2], ah[3], bl2, bl3);
            mma_bf16(sc[2 * kb2 + 1], al[0], al[1], al[2], al[3], bh2, bh3);
        }
    }

    // ---- scale + bias + mask, row max ----
    const int q_lo = q0 + gid, q_hi = q_lo + 8;
    float m0 = -1e30f, m1 = -1e30f;
    #pragma unroll
    for (int nb = 0; nb < 14; nb++) {
        #pragma unroll
        for (int c = 0; c < 2; c++) {
            const int k = kb0 + nb * 8 + tg * 2 + c;
            if (k < NKEY) {
                const int kd = (k * 74899) >> 20;
                const int km = k - kd * 14;
                sc[nb][c]     = sc[nb][c]     * SCALE + bwv[q_lo * 14 + km] + bhv[q_lo * 14 + kd];
                sc[nb][2 + c] = sc[nb][2 + c] * SCALE + bwv[q_hi * 14 + km] + bhv[q_hi * 14 + kd];
            } else {
                sc[nb][c] = -1e30f;
                sc[nb][2 + c] = -1e30f;
            }
            m0 = fmaxf(m0, sc[nb][c]);
            m1 = fmaxf(m1, sc[nb][2 + c]);
        }
    }
    m0 = fmaxf(m0, __shfl_xor_sync(0xffffffffu, m0, 1));
    m0 = fmaxf(m0, __shfl_xor_sync(0xffffffffu, m0, 2));
    m1 = fmaxf(m1, __shfl_xor_sync(0xffffffffu, m1, 1));
    m1 = fmaxf(m1, __shfl_xor_sync(0xffffffffu, m1, 2));
    if (tg == 0) {
        redm[(p * 2 + hf) * 16 + gid] = m0;
        redm[(p * 2 + hf) * 16 + gid + 8] = m1;
    }
    __syncthreads();
    m0 = fmaxf(redm[(p * 2) * 16 + gid], redm[(p * 2 + 1) * 16 + gid]);
    m1 = fmaxf(redm[(p * 2) * 16 + gid + 8], redm[(p * 2 + 1) * 16 + gid + 8]);

    float s0 = 0.f, s1 = 0.f;
    #pragma unroll
    for (int nb = 0; nb < 14; nb++) {
        #pragma unroll
        for (int c = 0; c < 2; c++) {
            sc[nb][c] = __expf(sc[nb][c] - m0);
            s0 += sc[nb][c];
            sc[nb][2 + c] = __expf(sc[nb][2 + c] - m1);
            s1 += sc[nb][2 + c];
        }
    }
    s0 += __shfl_xor_sync(0xffffffffu, s0, 1);
    s0 += __shfl_xor_sync(0xffffffffu, s0, 2);
    s1 += __shfl_xor_sync(0xffffffffu, s1, 1);
    s1 += __shfl_xor_sync(0xffffffffu, s1, 2);
    if (tg == 0) {
        reds[(p * 2 + hf) * 16 + gid] = s0;
        reds[(p * 2 + hf) * 16 + gid + 8] = s1;
    }
    __syncthreads();
    const float inv0 = 1.f / (reds[(p * 2) * 16 + gid] + reds[(p * 2 + 1) * 16 + gid]);
    const float inv1 = 1.f / (reds[(p * 2) * 16 + gid + 8] + reds[(p * 2 + 1) * 16 + gid + 8]);

    // ---- ctx = P @ V via trans-ldmatrix V, 3-term ----
    float acc[4][4];
    #pragma unroll
    for (int nd = 0; nd < 4; nd++)
        #pragma unroll
        for (int c = 0; c < 4; c++) acc[nd][c] = 0.f;

    const int v_rowoff = (((lane >> 3) & 1) << 3) + i8;
    const int v_col = (lane >> 4) << 3;

    #pragma unroll
    for (int kb = 0; kb < 7; kb++) {
        uint32_t pah[4], pal[4];
        split2(sc[2 * kb][0], sc[2 * kb][1], pah[0], pal[0]);
        split2(sc[2 * kb][2], sc[2 * kb][3], pah[1], pal[1]);
        split2(sc[2 * kb + 1][0], sc[2 * kb + 1][1], pah[2], pal[2]);
        split2(sc[2 * kb + 1][2], sc[2 * kb + 1][3], pah[3], pal[3]);

        const int vrow = kb0 + kb * 16 + v_rowoff;
        uint32_t vh[8], vl[8];
        ldm_x4t(vh[0], vh[1], vh[2], vh[3], uVh + (vrow * 40 + v_col) * 2);
        ldm_x4t(vh[4], vh[5], vh[6], vh[7], uVh + (vrow * 40 + 16 + v_col) * 2);
        ldm_x4t(vl[0], vl[1], vl[2], vl[3], uVl + (vrow * 40 + v_col) * 2);
        ldm_x4t(vl[4], vl[5], vl[6], vl[7], uVl + (vrow * 40 + 16 + v_col) * 2);

        #pragma unroll
        for (int nd = 0; nd < 4; nd++) {
            const uint32_t b0h = vh[(nd >> 1) * 4 + (nd & 1) * 2];
            const uint32_t b1h = vh[(nd >> 1) * 4 + (nd & 1) * 2 + 1];
            const uint32_t b0l = vl[(nd >> 1) * 4 + (nd & 1) * 2];
            const uint32_t b1l = vl[(nd >> 1) * 4 + (nd & 1) * 2 + 1];
            mma_bf16(acc[nd], pah[0], pah[1], pah[2], pah[3], b0h, b1h);
            mma_bf16(acc[nd], pah[0], pah[1], pah[2], pah[3], b0l, b1l);
            mma_bf16(acc[nd], pal[0], pal[1], pal[2], pal[3], b0h, b1h);
        }
    }

    // ---- combine halves, normalize, store bf16 hi/lo ctx ----
    if (hf == 0) {
        #pragma unroll
        for (int nd = 0; nd < 4; nd++) {
            *(float2*)&ctxb[(q0 + gid) * 32 + nd * 8 + tg * 2] = make_float2(acc[nd][0], acc[nd][1]);
            *(float2*)&ctxb[(q0 + gid + 8) * 32 + nd * 8 + tg * 2] = make_float2(acc[nd][2], acc[nd][3]);
        }
    }
    __syncthreads();
    if (hf == 1) {
        const size_t base = ((size_t)(b * NBLK + n) * NQ + q0 + gid) * CDIM + h * DHEAD;
        const size_t base8 = base + 8 * CDIM;
        #pragma unroll
        for (int nd = 0; nd < 4; nd++) {
            const int dcol = nd * 8 + tg * 2;
            const float2 o0 = *(const float2*)&ctxb[(q0 + gid) * 32 + dcol];
            const float2 o1 = *(const float2*)&ctxb[(q0 + gid + 8) * 32 + dcol];
            uint32_t hi, lo;
            split2((acc[nd][0] + o0.x) * inv0, (acc[nd][1] + o0.y) * inv0, hi, lo);
            *(uint32_t*)&g_ch[base + dcol] = hi;
            *(uint32_t*)&g_cl[base + dcol] = lo;
            split2((acc[nd][2] + o1.x) * inv1, (acc[nd][3] + o1.y) * inv1, hi, lo);
            *(uint32_t*)&g_ch[base8 + dcol] = hi;
            *(uint32_t*)&g_cl[base8 + dcol] = lo;
        }
    }
}

// ============================================================================
extern "C" void kernel_launch(void* const* d_in, const int* in_sizes, int n_in,
                              void* d_out, int out_size) {
    const float* x     = (const float*)d_in[0];
    const float* w_q   = (const float*)d_in[1];
    const float* w_kv  = (const float*)d_in[2];
    const float* fc_w  = (const float*)d_in[3];
    const float* fc_b  = (const float*)d_in[4];
    const float* rel_h = (const float*)d_in[5];
    const float* rel_w = (const float*)d_in[6];
    float* out = (float*)d_out;

    __nv_bfloat16 *xh, *xl, *qh, *ql, *kvh, *kvl, *ch, *cl, *wh, *wl;
    cudaGetSymbolAddress((void**)&xh, g_xh);
    cudaGetSymbolAddress((void**)&xl, g_xl);
    cudaGetSymbolAddress((void**)&qh, g_qh);
    cudaGetSymbolAddress((void**)&ql, g_ql);
    cudaGetSymbolAddress((void**)&kvh, g_kvh);
    cudaGetSymbolAddress((void**)&kvl, g_kvl);
    cudaGetSymbolAddress((void**)&ch, g_ch);
    cudaGetSymbolAddress((void**)&cl, g_cl);
    cudaGetSymbolAddress((void**)&wh, g_wh);
    cudaGetSymbolAddress((void**)&wl, g_wl);

    cudaFuncSetAttribute(halo_attn, cudaFuncAttributeMaxDynamicSharedMemorySize, ATT_SMEM);

    split_w<<<1024, 256>>>(w_q, w_kv, fc_w);
    transpose_x<<<dim3(NPIX / 32, CDIM / 32, BATCH), dim3(32, 8)>>>(x);
    gemm_mma<<<dim3(MTOT / 128, 2), 256>>>(xh, xl, wh, wl, qh, ql, CDIM, 0, nullptr, nullptr);
    gemm_mma<<<dim3(MTOT / 128, 4), 256>>>(xh, xl, wh + 256 * CDIM, wl + 256 * CDIM,
                                           kvh, kvl, 2 * CDIM, 0, nullptr, nullptr);
    halo_attn<<<BATCH * NBLK * HEADS, 256, ATT_SMEM>>>(rel_h, rel_w);
    gemm_mma<<<dim3(MTOT / 128, 2), 256>>>(ch, cl, wh + 768 * CDIM, wl + 768 * CDIM,
                                           nullptr, nullptr, 0, 1, fc_b, out);
}